// round 2
// baseline (speedup 1.0000x reference)
#include <cuda_runtime.h>
#include <cstdint>

#define D_MODEL 2048
#define N_HEADS 16
#define D_HEAD  128
#define SEQ     2048
#define BATCH   2
#define BS      (BATCH * SEQ)      // 4096
#define QKV_N   (3 * D_MODEL)      // 6144

// Scratch (allocation-free rule: __device__ globals)
__device__ float g_qkv[(size_t)BS * QKV_N];   // 96 MB
__device__ float g_att[(size_t)BS * D_MODEL]; // 32 MB

__device__ __forceinline__ float tf32r(float x) {
    asm("cvt.rna.tf32.f32 %0, %1;" : "=f"(x) : "f"(x));
    return x;
}
__device__ __forceinline__ uint32_t fbits(float x) { return __float_as_uint(x); }

__device__ __forceinline__ void mma8(float d[4], const uint32_t a[4], const uint32_t b[2]) {
    asm volatile(
        "mma.sync.aligned.m16n8k8.row.col.f32.tf32.tf32.f32 "
        "{%0,%1,%2,%3}, {%4,%5,%6,%7}, {%8,%9}, {%0,%1,%2,%3};\n"
        : "+f"(d[0]), "+f"(d[1]), "+f"(d[2]), "+f"(d[3])
        : "r"(a[0]), "r"(a[1]), "r"(a[2]), "r"(a[3]), "r"(b[0]), "r"(b[1]));
}

// ============================================================================
// Generic tf32 GEMM: C[M,N] = A[M,K] @ B[K,N] + bias[N]
// Block tile 128x128x32, 8 warps (4x2), warp tile 32x64.
// As[128][36] row-major (M x K), Bs[128][36] = B^T tile (N x K).
// Pad 36 -> frag load bank = (4r + k) % 32, conflict-free.
// ============================================================================
__global__ __launch_bounds__(256) void gemm_tf32(
    const float* __restrict__ A, const float* __restrict__ B,
    const float* __restrict__ bias, float* __restrict__ C,
    int M, int N, int K)
{
    __shared__ float As[128 * 36];
    __shared__ float Bs[128 * 36];

    const int tid  = threadIdx.x;
    const int lane = tid & 31;
    const int wid  = tid >> 5;
    const int wm   = wid >> 1;   // 0..3
    const int wn   = wid & 1;    // 0..1
    const int g    = lane >> 2;  // 0..7
    const int tig  = lane & 3;   // 0..3

    const int m0 = blockIdx.y * 128;
    const int n0 = blockIdx.x * 128;

    float acc[2][8][4];
#pragma unroll
    for (int mt = 0; mt < 2; mt++)
#pragma unroll
        for (int nt = 0; nt < 8; nt++)
#pragma unroll
            for (int i = 0; i < 4; i++) acc[mt][nt][i] = 0.f;

    for (int k0 = 0; k0 < K; k0 += 32) {
        // Load A tile 128x32 (float4, coalesced)
#pragma unroll
        for (int i = 0; i < 4; i++) {
            int r = (tid >> 3) + i * 32;
            int c = (tid & 7) * 4;
            float4 v = *(const float4*)(A + (size_t)(m0 + r) * K + k0 + c);
            v.x = tf32r(v.x); v.y = tf32r(v.y); v.z = tf32r(v.z); v.w = tf32r(v.w);
            *(float4*)(As + r * 36 + c) = v;
        }
        // Load B tile 32x128 transposed into Bs[n][k] (coalesced gmem reads)
#pragma unroll
        for (int i = 0; i < 16; i++) {
            int idx = tid + i * 256;
            int k = idx >> 7;
            int n = idx & 127;
            Bs[n * 36 + k] = tf32r(B[(size_t)(k0 + k) * N + n0 + n]);
        }
        __syncthreads();

#pragma unroll
        for (int ks = 0; ks < 4; ks++) {
            const int kk = ks * 8;
            uint32_t af[2][4];
#pragma unroll
            for (int mt = 0; mt < 2; mt++) {
                int r = wm * 32 + mt * 16 + g;
                af[mt][0] = fbits(As[r * 36 + kk + tig]);
                af[mt][1] = fbits(As[(r + 8) * 36 + kk + tig]);
                af[mt][2] = fbits(As[r * 36 + kk + tig + 4]);
                af[mt][3] = fbits(As[(r + 8) * 36 + kk + tig + 4]);
            }
            uint32_t bf[8][2];
#pragma unroll
            for (int nt = 0; nt < 8; nt++) {
                int n = wn * 64 + nt * 8 + g;
                bf[nt][0] = fbits(Bs[n * 36 + kk + tig]);
                bf[nt][1] = fbits(Bs[n * 36 + kk + tig + 4]);
            }
#pragma unroll
            for (int mt = 0; mt < 2; mt++)
#pragma unroll
                for (int nt = 0; nt < 8; nt++)
                    mma8(acc[mt][nt], af[mt], bf[nt]);
        }
        __syncthreads();
    }

    // Epilogue: + bias, store
#pragma unroll
    for (int mt = 0; mt < 2; mt++) {
        int r = m0 + wm * 32 + mt * 16 + g;
#pragma unroll
        for (int nt = 0; nt < 8; nt++) {
            int c = n0 + wn * 64 + nt * 8 + tig * 2;
            float b0 = bias[c], b1 = bias[c + 1];
            C[(size_t)r * N + c]           = acc[mt][nt][0] + b0;
            C[(size_t)r * N + c + 1]       = acc[mt][nt][1] + b1;
            C[(size_t)(r + 8) * N + c]     = acc[mt][nt][2] + b0;
            C[(size_t)(r + 8) * N + c + 1] = acc[mt][nt][3] + b1;
        }
    }
}

// ============================================================================
// Flash attention (causal), tf32 mma. BLOCK_M = BLOCK_N = 64, d = 128.
// Grid: (32 q-tiles, 16 heads, 2 batch). 256 threads (8 warps, 4x2).
// Warp S-tile 16x32, warp O-tile 16x64. Online softmax in fp32.
// ============================================================================
#define LDQ 132   // 128 + 4
#define LDV 68    // 64 + 4
#define LDP 68

__global__ __launch_bounds__(256) void attn_kernel(
    const float* __restrict__ qkv, float* __restrict__ out)
{
    extern __shared__ float sm[];
    float* Qs   = sm;                   // 64*132 = 8448
    float* Ks   = Qs + 64 * LDQ;        // 8448
    float* Vst  = Ks + 64 * LDQ;        // 128*68 = 8704  (V transposed: [d][kv])
    float* Ps   = Vst + 128 * LDV;      // 64*68 = 4352
    float* pmax = Ps + 64 * LDP;        // 2*64
    float* psum = pmax + 128;           // 2*64
    float* mrow = psum + 128;           // 64
    float* lrow = mrow + 64;            // 64

    const int tid  = threadIdx.x;
    const int lane = tid & 31;
    const int wid  = tid >> 5;
    const int wm   = wid >> 1;
    const int wn   = wid & 1;
    const int g    = lane >> 2;
    const int tig  = lane & 3;
    const int r1   = wm * 16 + g;   // local row 1
    const int r2   = r1 + 8;        // local row 2

    const int qt = blockIdx.x;   // q tile 0..31
    const int h  = blockIdx.y;
    const int b  = blockIdx.z;
    const int q0 = qt * 64;

    const float scale = 0.08838834764831845f; // 1/sqrt(128)
    const float* Qg = qkv + (size_t)b * SEQ * QKV_N + h * D_HEAD;
    const float* Kg = Qg + D_MODEL;
    const float* Vg = Qg + 2 * D_MODEL;

    if (tid < 64) { mrow[tid] = -3.0e38f; lrow[tid] = 0.f; }

    // Load Q tile 64x128, pre-scaled, tf32-rounded
    for (int i = tid; i < 64 * 32; i += 256) {
        int r = i >> 5;
        int c = (i & 31) * 4;
        float4 v = *(const float4*)(Qg + (size_t)(q0 + r) * QKV_N + c);
        v.x = tf32r(v.x * scale); v.y = tf32r(v.y * scale);
        v.z = tf32r(v.z * scale); v.w = tf32r(v.w * scale);
        *(float4*)(Qs + r * LDQ + c) = v;
    }

    float o[8][4];
#pragma unroll
    for (int nt = 0; nt < 8; nt++)
#pragma unroll
        for (int i = 0; i < 4; i++) o[nt][i] = 0.f;

    for (int j = 0; j <= qt; j++) {
        __syncthreads();  // previous PV-mma reads of Ks/Vst/Ps done; m/l updated; Qs ready
        const int kb = j * 64;
        // K tile 64x128 row-major (k-contig), float4 coalesced
        for (int i = tid; i < 64 * 32; i += 256) {
            int r = i >> 5;
            int c = (i & 31) * 4;
            float4 v = *(const float4*)(Kg + (size_t)(kb + r) * QKV_N + c);
            v.x = tf32r(v.x); v.y = tf32r(v.y); v.z = tf32r(v.z); v.w = tf32r(v.w);
            *(float4*)(Ks + r * LDQ + c) = v;
        }
        // V tile 64x128 transposed -> Vst[d][kv] (coalesced reads)
        for (int i = tid; i < 64 * 128; i += 256) {
            int k = i >> 7;
            int n = i & 127;
            Vst[n * LDV + k] = tf32r(Vg[(size_t)(kb + k) * QKV_N + n]);
        }
        __syncthreads();

        // S = Q @ K^T  (warp: 16 rows x 32 cols)
        float s[4][4];
#pragma unroll
        for (int nt = 0; nt < 4; nt++)
#pragma unroll
            for (int i = 0; i < 4; i++) s[nt][i] = 0.f;

#pragma unroll
        for (int ks = 0; ks < 16; ks++) {
            const int kk = ks * 8;
            uint32_t af[4];
            af[0] = fbits(Qs[r1 * LDQ + kk + tig]);
            af[1] = fbits(Qs[r2 * LDQ + kk + tig]);
            af[2] = fbits(Qs[r1 * LDQ + kk + tig + 4]);
            af[3] = fbits(Qs[r2 * LDQ + kk + tig + 4]);
#pragma unroll
            for (int nt = 0; nt < 4; nt++) {
                int n = wn * 32 + nt * 8 + g;
                uint32_t bf[2] = { fbits(Ks[n * LDQ + kk + tig]),
                                   fbits(Ks[n * LDQ + kk + tig + 4]) };
                mma8(s[nt], af, bf);
            }
        }

        // Causal mask on diagonal tile (kb == q0 -> local col > local row)
        if (j == qt) {
#pragma unroll
            for (int nt = 0; nt < 4; nt++) {
                int c0 = wn * 32 + nt * 8 + tig * 2;
                if (c0     > r1) s[nt][0] = -1e30f;
                if (c0 + 1 > r1) s[nt][1] = -1e30f;
                if (c0     > r2) s[nt][2] = -1e30f;
                if (c0 + 1 > r2) s[nt][3] = -1e30f;
            }
        }

        // Row max (quad reduce, then cross-warp via smem)
        float mx1 = -1e30f, mx2 = -1e30f;
#pragma unroll
        for (int nt = 0; nt < 4; nt++) {
            mx1 = fmaxf(mx1, fmaxf(s[nt][0], s[nt][1]));
            mx2 = fmaxf(mx2, fmaxf(s[nt][2], s[nt][3]));
        }
        mx1 = fmaxf(mx1, __shfl_xor_sync(0xffffffffu, mx1, 1));
        mx1 = fmaxf(mx1, __shfl_xor_sync(0xffffffffu, mx1, 2));
        mx2 = fmaxf(mx2, __shfl_xor_sync(0xffffffffu, mx2, 1));
        mx2 = fmaxf(mx2, __shfl_xor_sync(0xffffffffu, mx2, 2));
        if (tig == 0) { pmax[wn * 64 + r1] = mx1; pmax[wn * 64 + r2] = mx2; }
        __syncthreads();

        const float mo1 = mrow[r1], mo2 = mrow[r2];
        const float mn1 = fmaxf(mo1, fmaxf(pmax[r1], pmax[64 + r1]));
        const float mn2 = fmaxf(mo2, fmaxf(pmax[r2], pmax[64 + r2]));
        const float al1 = __expf(mo1 - mn1);
        const float al2 = __expf(mo2 - mn2);

        // P = exp(S - m_new), partial row sums
        float sm1 = 0.f, sm2 = 0.f;
#pragma unroll
        for (int nt = 0; nt < 4; nt++) {
            s[nt][0] = __expf(s[nt][0] - mn1);
            s[nt][1] = __expf(s[nt][1] - mn1);
            s[nt][2] = __expf(s[nt][2] - mn2);
            s[nt][3] = __expf(s[nt][3] - mn2);
            sm1 += s[nt][0] + s[nt][1];
            sm2 += s[nt][2] + s[nt][3];
        }
        sm1 += __shfl_xor_sync(0xffffffffu, sm1, 1);
        sm1 += __shfl_xor_sync(0xffffffffu, sm1, 2);
        sm2 += __shfl_xor_sync(0xffffffffu, sm2, 1);
        sm2 += __shfl_xor_sync(0xffffffffu, sm2, 2);
        if (tig == 0) { psum[wn * 64 + r1] = sm1; psum[wn * 64 + r2] = sm2; }

        // Rescale O accumulators
#pragma unroll
        for (int nt = 0; nt < 8; nt++) {
            o[nt][0] *= al1; o[nt][1] *= al1;
            o[nt][2] *= al2; o[nt][3] *= al2;
        }

        // Write P to smem (tf32-rounded) for the PV mma
#pragma unroll
        for (int nt = 0; nt < 4; nt++) {
            int c = wn * 32 + nt * 8 + tig * 2;
            Ps[r1 * LDP + c]     = tf32r(s[nt][0]);
            Ps[r1 * LDP + c + 1] = tf32r(s[nt][1]);
            Ps[r2 * LDP + c]     = tf32r(s[nt][2]);
            Ps[r2 * LDP + c + 1] = tf32r(s[nt][3]);
        }
        __syncthreads();

        // Update m, l (one writer per row)
        if (wn == 0 && tig == 0) {
            lrow[r1] = al1 * lrow[r1] + psum[r1] + psum[64 + r1];
            lrow[r2] = al2 * lrow[r2] + psum[r2] + psum[64 + r2];
            mrow[r1] = mn1;
            mrow[r2] = mn2;
        }

        // O += P @ V  (warp: 16 rows x 64 cols, K = 64)
#pragma unroll
        for (int ks = 0; ks < 8; ks++) {
            const int kk = ks * 8;
            uint32_t af[4];
            af[0] = fbits(Ps[r1 * LDP + kk + tig]);
            af[1] = fbits(Ps[r2 * LDP + kk + tig]);
            af[2] = fbits(Ps[r1 * LDP + kk + tig + 4]);
            af[3] = fbits(Ps[r2 * LDP + kk + tig + 4]);
#pragma unroll
            for (int nt = 0; nt < 8; nt++) {
                int n = wn * 64 + nt * 8 + g;
                uint32_t bf[2] = { fbits(Vst[n * LDV + kk + tig]),
                                   fbits(Vst[n * LDV + kk + tig + 4]) };
                mma8(o[nt], af, bf);
            }
        }
    }

    __syncthreads();
    const float inv1 = 1.f / lrow[r1];
    const float inv2 = 1.f / lrow[r2];

    float* Og = out + ((size_t)b * SEQ + q0) * D_MODEL + h * D_HEAD;
#pragma unroll
    for (int nt = 0; nt < 8; nt++) {
        int c = wn * 64 + nt * 8 + tig * 2;
        Og[(size_t)r1 * D_MODEL + c]     = o[nt][0] * inv1;
        Og[(size_t)r1 * D_MODEL + c + 1] = o[nt][1] * inv1;
        Og[(size_t)r2 * D_MODEL + c]     = o[nt][2] * inv2;
        Og[(size_t)r2 * D_MODEL + c + 1] = o[nt][3] * inv2;
    }
}

// ============================================================================
// Launch
// ============================================================================
#define ATTN_SMEM_BYTES ((64*LDQ + 64*LDQ + 128*LDV + 64*LDP + 128 + 128 + 64 + 64) * sizeof(float))

extern "C" void kernel_launch(void* const* d_in, const int* in_sizes, int n_in,
                              void* d_out, int out_size) {
    const float* x    = (const float*)d_in[0];
    const float* Wqkv = (const float*)d_in[1];
    const float* bqkv = (const float*)d_in[2];
    const float* Wout = (const float*)d_in[3];
    const float* bout = (const float*)d_in[4];
    float* out = (float*)d_out;

    float *qkv_p, *att_p;
    cudaGetSymbolAddress((void**)&qkv_p, g_qkv);
    cudaGetSymbolAddress((void**)&att_p, g_att);

    cudaFuncSetAttribute(attn_kernel, cudaFuncAttributeMaxDynamicSharedMemorySize,
                         (int)ATTN_SMEM_BYTES);

    // 1) qkv = x @ W_qkv + b_qkv   [4096, 6144]
    gemm_tf32<<<dim3(QKV_N / 128, BS / 128), 256>>>(x, Wqkv, bqkv, qkv_p, BS, QKV_N, D_MODEL);

    // 2) causal flash attention -> g_att [4096, 2048] (head-interleaved = transposed back)
    attn_kernel<<<dim3(SEQ / 64, N_HEADS, BATCH), 256, ATTN_SMEM_BYTES>>>(qkv_p, att_p);

    // 3) out = att @ W_out + b_out  [4096, 2048]
    gemm_tf32<<<dim3(D_MODEL / 128, BS / 128), 256>>>(att_p, Wout, bout, out, BS, D_MODEL, D_MODEL);
}

// round 4
// speedup vs baseline: 1.6234x; 1.6234x over previous
#include <cuda_runtime.h>
#include <cstdint>

#define D_MODEL 2048
#define N_HEADS 16
#define D_HEAD  128
#define SEQ     2048
#define BATCH   2
#define BS      (BATCH * SEQ)      // 4096
#define QKV_N   (3 * D_MODEL)      // 6144

// Scratch (allocation-free rule: __device__ globals)
__device__ float g_qkv[(size_t)BS * QKV_N];          // 96 MB (tf32, rounded)
__device__ float g_att[(size_t)BS * D_MODEL];        // 32 MB (tf32, rounded)
__device__ float g_x[(size_t)BS * D_MODEL];          // 32 MB (tf32-rounded x)
__device__ float g_wqkvT[(size_t)QKV_N * D_MODEL];   // 48 MB (W_qkv^T, rounded)
__device__ float g_woutT[(size_t)D_MODEL * D_MODEL]; // 16 MB (W_out^T, rounded)

__device__ __forceinline__ float tf32r(float x) {
    asm("cvt.rna.tf32.f32 %0, %1;" : "=f"(x) : "f"(x));
    return x;
}

__device__ __forceinline__ uint32_t smem_u32(const void* p) {
    uint32_t a;
    asm("{ .reg .u64 t; cvta.to.shared.u64 t, %1; cvt.u32.u64 %0, t; }" : "=r"(a) : "l"(p));
    return a;
}

__device__ __forceinline__ void mma8(float d[4], const uint32_t a[4], const uint32_t b[2]) {
    asm volatile(
        "mma.sync.aligned.m16n8k8.row.col.f32.tf32.tf32.f32 "
        "{%0,%1,%2,%3}, {%4,%5,%6,%7}, {%8,%9}, {%0,%1,%2,%3};\n"
        : "+f"(d[0]), "+f"(d[1]), "+f"(d[2]), "+f"(d[3])
        : "r"(a[0]), "r"(a[1]), "r"(a[2]), "r"(a[3]), "r"(b[0]), "r"(b[1]));
}

// ldmatrix x4: four 8x8 b16 matrices == 16x8 f32 tile in two column-quadrants.
#define LDSM4(R0, R1, R2, R3, ADDR) \
    asm volatile("ldmatrix.sync.aligned.m8n8.x4.shared.b16 {%0,%1,%2,%3}, [%4];" \
                 : "=r"(R0), "=r"(R1), "=r"(R2), "=r"(R3) : "r"(ADDR))

__device__ __forceinline__ void cpasync16(uint32_t dst, const void* src) {
    asm volatile("cp.async.cg.shared.global [%0], [%1], 16;" :: "r"(dst), "l"(src) : "memory");
}
__device__ __forceinline__ void cp_commit() {
    asm volatile("cp.async.commit_group;" ::: "memory");
}
__device__ __forceinline__ void cp_wait1() {
    asm volatile("cp.async.wait_group 1;" ::: "memory");
}

// ============================================================================
// Prep kernels: tf32-round copy + transpose-round for weights.
// ============================================================================
__global__ void round_copy4(const float* __restrict__ in, float* __restrict__ out, int n4) {
    int i = blockIdx.x * blockDim.x + threadIdx.x;
    if (i < n4) {
        float4 v = ((const float4*)in)[i];
        v.x = tf32r(v.x); v.y = tf32r(v.y); v.z = tf32r(v.z); v.w = tf32r(v.w);
        ((float4*)out)[i] = v;
    }
}

// W [K][N] -> Wt [N][K], tf32-rounded
__global__ void transpose_round(const float* __restrict__ W, float* __restrict__ Wt,
                                int K, int N) {
    __shared__ float t[32][33];
    int n0 = blockIdx.x * 32, k0 = blockIdx.y * 32;
    int tx = threadIdx.x, ty = threadIdx.y;
#pragma unroll
    for (int i = ty; i < 32; i += 8)
        t[i][tx] = tf32r(W[(size_t)(k0 + i) * N + n0 + tx]);
    __syncthreads();
#pragma unroll
    for (int i = ty; i < 32; i += 8)
        Wt[(size_t)(n0 + i) * K + k0 + tx] = t[tx][i];
}

// ============================================================================
// tf32 GEMM, mma.sync + ldmatrix + cp.async double buffer.
// C[M,N] = A[M,K] @ Bt[N,K]^T + bias[N].  A, Bt pre-rounded to tf32.
// Block 128x128x32, 8 warps (4x2), warp tile 32x64.
// As/Bs: [128][36] padded (row stride 144B: cp.async 16B-aligned, ldmatrix
// 8-row matrices cover all 32 banks).
// ============================================================================
#define GAF 4608                       // 128*36 floats per operand tile
#define G_STAGE_BYTES (2 * GAF * 4)    // 36864
#define G_SMEM_BYTES (2 * G_STAGE_BYTES)

__global__ __launch_bounds__(256, 2) void gemm_lm(
    const float* __restrict__ A, const float* __restrict__ Bt,
    const float* __restrict__ bias, float* __restrict__ C,
    int M, int N, int K, int round_out)
{
    extern __shared__ float smem[];
    const uint32_t sbase = smem_u32(smem);

    const int tid  = threadIdx.x;
    const int lane = tid & 31;
    const int wid  = tid >> 5;
    const int wm   = wid >> 1;
    const int wn   = wid & 1;
    const int g    = lane >> 2;
    const int tig  = lane & 3;

    const int m0 = blockIdx.y * 128;
    const int n0 = blockIdx.x * 128;
    const float* Ag = A + (size_t)m0 * K;
    const float* Bg = Bt + (size_t)n0 * K;
    const int nslab = K >> 5;

    // cp.async thread mapping: 4 chunks of 16B per operand per thread
    const int crow = tid >> 3;       // 0..31 (base row)
    const int ccj  = (tid & 7) * 4;  // float col within 32

    // ldmatrix per-lane base offsets
    const int lmrow = lane & 15;
    const int lmc4  = (lane >> 4) * 4;
    const uint32_t a_lm = sbase + (((wm * 32 + lmrow) * 36 + lmc4) << 2);
    const uint32_t b_lm = sbase + (uint32_t)(GAF * 4) + (((wn * 64 + lmrow) * 36 + lmc4) << 2);

    float acc[2][8][4];
#pragma unroll
    for (int mt = 0; mt < 2; mt++)
#pragma unroll
        for (int nt = 0; nt < 8; nt++)
#pragma unroll
            for (int i = 0; i < 4; i++) acc[mt][nt][i] = 0.f;

    // slab loader
    auto load_slab = [&](int i, int s) {
        const uint32_t ab = sbase + (uint32_t)s * G_STAGE_BYTES;
        const uint32_t bb = ab + (uint32_t)(GAF * 4);
        const int k0 = i << 5;
#pragma unroll
        for (int r = 0; r < 4; r++) {
            int row = crow + r * 32;
            cpasync16(ab + ((row * 36 + ccj) << 2), Ag + (size_t)row * K + k0 + ccj);
        }
#pragma unroll
        for (int r = 0; r < 4; r++) {
            int row = crow + r * 32;
            cpasync16(bb + ((row * 36 + ccj) << 2), Bg + (size_t)row * K + k0 + ccj);
        }
        cp_commit();
    };

    load_slab(0, 0);
    load_slab(1, 1);

    for (int i = 0; i < nslab; i++) {
        cp_wait1();
        __syncthreads();
        const int s = i & 1;
        const uint32_t a_st = a_lm + (uint32_t)s * G_STAGE_BYTES;
        const uint32_t b_st = b_lm + (uint32_t)s * G_STAGE_BYTES;

#pragma unroll
        for (int ks = 0; ks < 4; ks++) {
            const uint32_t ka = a_st + ks * 32;
            uint32_t af0[4], af1[4];
            LDSM4(af0[0], af0[1], af0[2], af0[3], ka);
            LDSM4(af1[0], af1[1], af1[2], af1[3], ka + 2304);  // +16 rows
            const uint32_t kb = b_st + ks * 32;
#pragma unroll
            for (int q = 0; q < 4; q++) {
                uint32_t b0, b1, b2, b3;
                LDSM4(b0, b1, b2, b3, kb + q * 2304);
                uint32_t bfA[2] = { b0, b2 };
                uint32_t bfB[2] = { b1, b3 };
                mma8(acc[0][2 * q],     af0, bfA);
                mma8(acc[0][2 * q + 1], af0, bfB);
                mma8(acc[1][2 * q],     af1, bfA);
                mma8(acc[1][2 * q + 1], af1, bfB);
            }
        }
        __syncthreads();
        if (i + 2 < nslab) load_slab(i + 2, s);
        else cp_commit();   // keep group count consistent
    }

    // Epilogue
#pragma unroll
    for (int mt = 0; mt < 2; mt++) {
        int r = m0 + wm * 32 + mt * 16 + g;
#pragma unroll
        for (int nt = 0; nt < 8; nt++) {
            int c = n0 + wn * 64 + nt * 8 + tig * 2;
            float b0 = bias[c], b1 = bias[c + 1];
            float v0 = acc[mt][nt][0] + b0;
            float v1 = acc[mt][nt][1] + b1;
            float v2 = acc[mt][nt][2] + b0;
            float v3 = acc[mt][nt][3] + b1;
            if (round_out) { v0 = tf32r(v0); v1 = tf32r(v1); v2 = tf32r(v2); v3 = tf32r(v3); }
            *(float2*)(C + (size_t)r * N + c)       = make_float2(v0, v1);
            *(float2*)(C + (size_t)(r + 8) * N + c) = make_float2(v2, v3);
        }
    }
}

// ============================================================================
// Flash attention (causal), tf32 mma.sync + ldmatrix, warp-owns-rows.
// BLOCK_M = 128 (8 warps x 16 rows), BLOCK_N = 64. Softmax entirely in
// registers + quad shuffles (no cross-warp reductions).
// qkv is pre-rounded tf32 (GEMM1 epilogue), so K/V need no re-round.
// ============================================================================
#define LDQ 132   // Q/K row stride (128 + 4)
#define LDV 68    // Vst/Ps row stride (64 + 4)
#define ATTN_SMEM_FLOATS (128 * LDQ + 64 * LDQ + 128 * LDV + 128 * LDV)
#define ATTN_SMEM_BYTES (ATTN_SMEM_FLOATS * 4)

__global__ __launch_bounds__(256) void attn_kernel(
    const float* __restrict__ qkv, float* __restrict__ out)
{
    extern __shared__ float sm[];
    float* Qs  = sm;                  // [128][132]
    float* Ks  = Qs + 128 * LDQ;      // [64][132]   (row = kv, col = d)
    float* Vst = Ks + 64 * LDQ;       // [128][68]   (row = d, col = kv)
    float* Ps  = Vst + 128 * LDV;     // [128][68]   (row = q, col = kv)

    const int tid  = threadIdx.x;
    const int lane = tid & 31;
    const int wid  = tid >> 5;        // 0..7
    const int g    = lane >> 2;
    const int tig  = lane & 3;
    const int rbase = wid * 16;
    const int r1 = rbase + g;
    const int r2 = r1 + 8;

    const int qt = blockIdx.x;        // 0..15
    const int h  = blockIdx.y;
    const int b  = blockIdx.z;
    const int q0 = qt * 128;

    const float scale = 0.08838834764831845f; // 1/sqrt(128)
    const float* Qg = qkv + (size_t)b * SEQ * QKV_N + h * D_HEAD;
    const float* Kg = Qg + D_MODEL;
    const float* Vg = Qg + 2 * D_MODEL;

    // ldmatrix lane offsets
    const int lmrow = lane & 15;
    const int lmc4  = (lane >> 4) * 4;
    const uint32_t sb = smem_u32(sm);
    const uint32_t q_lm = sb + (((rbase + lmrow) * LDQ + lmc4) << 2);
    const uint32_t k_lm = sb + ((128 * LDQ + lmrow * LDQ + lmc4) << 2);
    const uint32_t v_lm = sb + (((128 + 64) * LDQ + lmrow * LDV + lmc4) << 2);
    const uint32_t p_lm = sb + (((128 + 64) * LDQ + 128 * LDV + (rbase + lmrow) * LDV + lmc4) << 2);

    // Load Q tile 128x128 (pre-scaled, re-rounded)
    for (int i = tid; i < 128 * 32; i += 256) {
        int r = i >> 5;
        int c = (i & 31) * 4;
        float4 v = *(const float4*)(Qg + (size_t)(q0 + r) * QKV_N + c);
        v.x = tf32r(v.x * scale); v.y = tf32r(v.y * scale);
        v.z = tf32r(v.z * scale); v.w = tf32r(v.w * scale);
        *(float4*)(Qs + r * LDQ + c) = v;
    }

    float o[16][4];
#pragma unroll
    for (int nt = 0; nt < 16; nt++)
#pragma unroll
        for (int i = 0; i < 4; i++) o[nt][i] = 0.f;
    float m1 = -1e30f, m2 = -1e30f, l1 = 0.f, l2 = 0.f;

    const int njt = 2 * qt + 2;   // kv tiles
    for (int j = 0; j < njt; j++) {
        __syncthreads();   // Ks/Vst reuse; also covers initial Qs visibility
        const int kb = j * 64;
        // K tile 64x128 (row = kv, col = d), float4 coalesced
        for (int i = tid; i < 64 * 32; i += 256) {
            int r = i >> 5;
            int c = (i & 31) * 4;
            *(float4*)(Ks + r * LDQ + c) =
                *(const float4*)(Kg + (size_t)(kb + r) * QKV_N + c);
        }
        // V tile transposed -> Vst[d][kv]; per-thread: 4 coalesced scalar loads,
        // one float4 STS (conflict-free: lanes n consecutive, 16B rows span banks)
        for (int i = tid; i < 128 * 16; i += 256) {
            int n  = i & 127;       // d index
            int k4 = i >> 7;        // kv/4
            float4 v;
            v.x = Vg[(size_t)(kb + k4 * 4 + 0) * QKV_N + n];
            v.y = Vg[(size_t)(kb + k4 * 4 + 1) * QKV_N + n];
            v.z = Vg[(size_t)(kb + k4 * 4 + 2) * QKV_N + n];
            v.w = Vg[(size_t)(kb + k4 * 4 + 3) * QKV_N + n];
            *(float4*)(Vst + n * LDV + k4 * 4) = v;
        }
        __syncthreads();

        // ---- S = Q @ K^T : warp tile 16 x 64, K-dim 128 ----
        float s[8][4];
#pragma unroll
        for (int nt = 0; nt < 8; nt++)
#pragma unroll
            for (int i = 0; i < 4; i++) s[nt][i] = 0.f;

#pragma unroll
        for (int ks = 0; ks < 16; ks++) {
            uint32_t af[4];
            LDSM4(af[0], af[1], af[2], af[3], q_lm + ks * 32);
            const uint32_t kbb = k_lm + ks * 32;
#pragma unroll
            for (int q = 0; q < 4; q++) {
                uint32_t b0, b1, b2, b3;
                LDSM4(b0, b1, b2, b3, kbb + q * (16 * LDQ * 4));
                uint32_t bfA[2] = { b0, b2 };
                uint32_t bfB[2] = { b1, b3 };
                mma8(s[2 * q],     af, bfA);
                mma8(s[2 * q + 1], af, bfB);
            }
        }

        // ---- causal mask (only the last two kv tiles can clip) ----
        if (j >= 2 * qt) {
            const int koff = (j - 2 * qt) << 6;
            const int lim1 = r1 - koff;
            const int lim2 = r2 - koff;
#pragma unroll
            for (int nt = 0; nt < 8; nt++) {
                int c0 = nt * 8 + tig * 2;
                if (c0     > lim1) s[nt][0] = -1e30f;
                if (c0 + 1 > lim1) s[nt][1] = -1e30f;
                if (c0     > lim2) s[nt][2] = -1e30f;
                if (c0 + 1 > lim2) s[nt][3] = -1e30f;
            }
        }

        // ---- online softmax, in-warp only ----
        float mx1 = -1e30f, mx2 = -1e30f;
#pragma unroll
        for (int nt = 0; nt < 8; nt++) {
            mx1 = fmaxf(mx1, fmaxf(s[nt][0], s[nt][1]));
            mx2 = fmaxf(mx2, fmaxf(s[nt][2], s[nt][3]));
        }
        mx1 = fmaxf(mx1, __shfl_xor_sync(0xffffffffu, mx1, 1));
        mx1 = fmaxf(mx1, __shfl_xor_sync(0xffffffffu, mx1, 2));
        mx2 = fmaxf(mx2, __shfl_xor_sync(0xffffffffu, mx2, 1));
        mx2 = fmaxf(mx2, __shfl_xor_sync(0xffffffffu, mx2, 2));

        const float mn1 = fmaxf(m1, mx1);
        const float mn2 = fmaxf(m2, mx2);
        const float al1 = __expf(m1 - mn1);
        const float al2 = __expf(m2 - mn2);

        float sm1 = 0.f, sm2 = 0.f;
#pragma unroll
        for (int nt = 0; nt < 8; nt++) {
            s[nt][0] = __expf(s[nt][0] - mn1);
            s[nt][1] = __expf(s[nt][1] - mn1);
            s[nt][2] = __expf(s[nt][2] - mn2);
            s[nt][3] = __expf(s[nt][3] - mn2);
            sm1 += s[nt][0] + s[nt][1];
            sm2 += s[nt][2] + s[nt][3];
        }
        sm1 += __shfl_xor_sync(0xffffffffu, sm1, 1);
        sm1 += __shfl_xor_sync(0xffffffffu, sm1, 2);
        sm2 += __shfl_xor_sync(0xffffffffu, sm2, 1);
        sm2 += __shfl_xor_sync(0xffffffffu, sm2, 2);

        l1 = al1 * l1 + sm1;
        l2 = al2 * l2 + sm2;
        m1 = mn1;
        m2 = mn2;

        // rescale O
#pragma unroll
        for (int nt = 0; nt < 16; nt++) {
            o[nt][0] *= al1; o[nt][1] *= al1;
            o[nt][2] *= al2; o[nt][3] *= al2;
        }

        // write P (tf32) to warp-private Ps rows
#pragma unroll
        for (int nt = 0; nt < 8; nt++) {
            int c = nt * 8 + tig * 2;
            *(float2*)(Ps + r1 * LDV + c) = make_float2(tf32r(s[nt][0]), tf32r(s[nt][1]));
            *(float2*)(Ps + r2 * LDV + c) = make_float2(tf32r(s[nt][2]), tf32r(s[nt][3]));
        }
        __syncwarp();

        // ---- O += P @ V : warp tile 16 x 128, K-dim 64 ----
#pragma unroll
        for (int ks = 0; ks < 8; ks++) {
            uint32_t af[4];
            LDSM4(af[0], af[1], af[2], af[3], p_lm + ks * 32);
            const uint32_t vb = v_lm + ks * 32;
#pragma unroll
            for (int q = 0; q < 8; q++) {
                uint32_t b0, b1, b2, b3;
                LDSM4(b0, b1, b2, b3, vb + q * (16 * LDV * 4));
                uint32_t bfA[2] = { b0, b2 };
                uint32_t bfB[2] = { b1, b3 };
                mma8(o[2 * q],     af, bfA);
                mma8(o[2 * q + 1], af, bfB);
            }
        }
        __syncwarp();
    }

    const float inv1 = 1.f / l1;
    const float inv2 = 1.f / l2;
    float* Og = out + ((size_t)b * SEQ + q0) * D_MODEL + h * D_HEAD;
#pragma unroll
    for (int nt = 0; nt < 16; nt++) {
        int c = nt * 8 + tig * 2;
        *(float2*)(Og + (size_t)r1 * D_MODEL + c) =
            make_float2(tf32r(o[nt][0] * inv1), tf32r(o[nt][1] * inv1));
        *(float2*)(Og + (size_t)r2 * D_MODEL + c) =
            make_float2(tf32r(o[nt][2] * inv2), tf32r(o[nt][3] * inv2));
    }
}

// ============================================================================
// Launch
// ============================================================================
extern "C" void kernel_launch(void* const* d_in, const int* in_sizes, int n_in,
                              void* d_out, int out_size) {
    const float* x    = (const float*)d_in[0];
    const float* Wqkv = (const float*)d_in[1];
    const float* bqkv = (const float*)d_in[2];
    const float* Wout = (const float*)d_in[3];
    const float* bout = (const float*)d_in[4];
    float* out = (float*)d_out;

    float *qkv_p, *att_p, *x_p, *wqkvT_p, *woutT_p;
    cudaGetSymbolAddress((void**)&qkv_p, g_qkv);
    cudaGetSymbolAddress((void**)&att_p, g_att);
    cudaGetSymbolAddress((void**)&x_p, g_x);
    cudaGetSymbolAddress((void**)&wqkvT_p, g_wqkvT);
    cudaGetSymbolAddress((void**)&woutT_p, g_woutT);

    cudaFuncSetAttribute(gemm_lm, cudaFuncAttributeMaxDynamicSharedMemorySize,
                         (int)G_SMEM_BYTES);
    cudaFuncSetAttribute(attn_kernel, cudaFuncAttributeMaxDynamicSharedMemorySize,
                         (int)ATTN_SMEM_BYTES);

    // Prep: round x; transpose+round weights (tf32 operands for cp.async path)
    {
        int n4 = BS * D_MODEL / 4;
        round_copy4<<<(n4 + 255) / 256, 256>>>(x, x_p, n4);
        transpose_round<<<dim3(QKV_N / 32, D_MODEL / 32), dim3(32, 8)>>>(Wqkv, wqkvT_p, D_MODEL, QKV_N);
        transpose_round<<<dim3(D_MODEL / 32, D_MODEL / 32), dim3(32, 8)>>>(Wout, woutT_p, D_MODEL, D_MODEL);
    }

    // 1) qkv = x @ W_qkv + b_qkv   [4096, 6144], output tf32-rounded
    gemm_lm<<<dim3(QKV_N / 128, BS / 128), 256, G_SMEM_BYTES>>>(
        x_p, wqkvT_p, bqkv, qkv_p, BS, QKV_N, D_MODEL, 1);

    // 2) causal flash attention -> g_att (tf32-rounded)
    attn_kernel<<<dim3(SEQ / 128, N_HEADS, BATCH), 256, ATTN_SMEM_BYTES>>>(qkv_p, att_p);

    // 3) out = att @ W_out + b_out  [4096, 2048]
    gemm_lm<<<dim3(D_MODEL / 128, BS / 128), 256, G_SMEM_BYTES>>>(
        att_p, woutT_p, bout, out, BS, D_MODEL, D_MODEL, 0);
}

// round 5
// speedup vs baseline: 1.8161x; 1.1187x over previous
#include <cuda_runtime.h>
#include <cstdint>

#define D_MODEL 2048
#define N_HEADS 16
#define D_HEAD  128
#define SEQ     2048
#define BATCH   2
#define BS      (BATCH * SEQ)      // 4096
#define QKV_N   (3 * D_MODEL)      // 6144

// Scratch (allocation-free rule: __device__ globals)
__device__ float g_qkv[(size_t)BS * QKV_N];          // 96 MB (tf32, rounded)
__device__ float g_att[(size_t)BS * D_MODEL];        // 32 MB (tf32, rounded)
__device__ float g_x[(size_t)BS * D_MODEL];          // 32 MB (tf32-rounded x)
__device__ float g_wqkvT[(size_t)QKV_N * D_MODEL];   // 48 MB (W_qkv^T, rounded)
__device__ float g_woutT[(size_t)D_MODEL * D_MODEL]; // 16 MB (W_out^T, rounded)

__device__ __forceinline__ float tf32r(float x) {
    asm("cvt.rna.tf32.f32 %0, %1;" : "=f"(x) : "f"(x));
    return x;
}

__device__ __forceinline__ uint32_t smem_u32(const void* p) {
    uint32_t a;
    asm("{ .reg .u64 t; cvta.to.shared.u64 t, %1; cvt.u32.u64 %0, t; }" : "=r"(a) : "l"(p));
    return a;
}

__device__ __forceinline__ void mma8(float d[4], const uint32_t a[4], const uint32_t b[2]) {
    asm volatile(
        "mma.sync.aligned.m16n8k8.row.col.f32.tf32.tf32.f32 "
        "{%0,%1,%2,%3}, {%4,%5,%6,%7}, {%8,%9}, {%0,%1,%2,%3};\n"
        : "+f"(d[0]), "+f"(d[1]), "+f"(d[2]), "+f"(d[3])
        : "r"(a[0]), "r"(a[1]), "r"(a[2]), "r"(a[3]), "r"(b[0]), "r"(b[1]));
}

#define LDSM4(R0, R1, R2, R3, ADDR) \
    asm volatile("ldmatrix.sync.aligned.m8n8.x4.shared.b16 {%0,%1,%2,%3}, [%4];" \
                 : "=r"(R0), "=r"(R1), "=r"(R2), "=r"(R3) : "r"(ADDR))

__device__ __forceinline__ void cpasync16(uint32_t dst, const void* src) {
    asm volatile("cp.async.cg.shared.global [%0], [%1], 16;" :: "r"(dst), "l"(src) : "memory");
}
__device__ __forceinline__ void cp_commit() {
    asm volatile("cp.async.commit_group;" ::: "memory");
}
__device__ __forceinline__ void cp_wait0() {
    asm volatile("cp.async.wait_group 0;" ::: "memory");
}
__device__ __forceinline__ void cp_wait1() {
    asm volatile("cp.async.wait_group 1;" ::: "memory");
}

// ============================================================================
// Prep kernels
// ============================================================================
__global__ void round_copy4(const float* __restrict__ in, float* __restrict__ out, int n4) {
    int i = blockIdx.x * blockDim.x + threadIdx.x;
    if (i < n4) {
        float4 v = ((const float4*)in)[i];
        v.x = tf32r(v.x); v.y = tf32r(v.y); v.z = tf32r(v.z); v.w = tf32r(v.w);
        ((float4*)out)[i] = v;
    }
}

__global__ void transpose_round(const float* __restrict__ W, float* __restrict__ Wt,
                                int K, int N) {
    __shared__ float t[32][33];
    int n0 = blockIdx.x * 32, k0 = blockIdx.y * 32;
    int tx = threadIdx.x, ty = threadIdx.y;
#pragma unroll
    for (int i = ty; i < 32; i += 8)
        t[i][tx] = tf32r(W[(size_t)(k0 + i) * N + n0 + tx]);
    __syncthreads();
#pragma unroll
    for (int i = ty; i < 32; i += 8)
        Wt[(size_t)(n0 + i) * K + k0 + tx] = t[tx][i];
}

// ============================================================================
// tf32 GEMM: 3-stage cp.async ring, single __syncthreads per K-slab.
// C[M,N] = A[M,K] @ Bt[N,K]^T + bias[N].  Block 128x128x32, 8 warps (4x2).
// ============================================================================
#define GAF 4608                       // 128*36 floats per operand tile
#define G_STAGE_BYTES (2u * GAF * 4u)  // 36864
#define G_SMEM_BYTES (3u * G_STAGE_BYTES)

__global__ __launch_bounds__(256, 2) void gemm_lm(
    const float* __restrict__ A, const float* __restrict__ Bt,
    const float* __restrict__ bias, float* __restrict__ C,
    int M, int N, int K, int round_out)
{
    extern __shared__ float smem[];
    const uint32_t sbase = smem_u32(smem);

    const int tid  = threadIdx.x;
    const int lane = tid & 31;
    const int wid  = tid >> 5;
    const int wm   = wid >> 1;
    const int wn   = wid & 1;
    const int g    = lane >> 2;
    const int tig  = lane & 3;

    const int m0 = blockIdx.y * 128;
    const int n0 = blockIdx.x * 128;
    const float* Ag = A + (size_t)m0 * K;
    const float* Bg = Bt + (size_t)n0 * K;
    const int nslab = K >> 5;

    const int crow = tid >> 3;
    const int ccj  = (tid & 7) * 4;

    const int lmrow = lane & 15;
    const int lmc4  = (lane >> 4) * 4;
    const uint32_t a_lm = sbase + (((wm * 32 + lmrow) * 36 + lmc4) << 2);
    const uint32_t b_lm = sbase + (uint32_t)(GAF * 4) + (((wn * 64 + lmrow) * 36 + lmc4) << 2);

    float acc[2][8][4];
#pragma unroll
    for (int mt = 0; mt < 2; mt++)
#pragma unroll
        for (int nt = 0; nt < 8; nt++)
#pragma unroll
            for (int i = 0; i < 4; i++) acc[mt][nt][i] = 0.f;

    auto load_slab = [&](int i, int s) {
        const uint32_t ab = sbase + (uint32_t)s * G_STAGE_BYTES;
        const uint32_t bb = ab + (uint32_t)(GAF * 4);
        const int k0 = i << 5;
#pragma unroll
        for (int r = 0; r < 4; r++) {
            int row = crow + r * 32;
            cpasync16(ab + ((row * 36 + ccj) << 2), Ag + (size_t)row * K + k0 + ccj);
        }
#pragma unroll
        for (int r = 0; r < 4; r++) {
            int row = crow + r * 32;
            cpasync16(bb + ((row * 36 + ccj) << 2), Bg + (size_t)row * K + k0 + ccj);
        }
        cp_commit();
    };

    load_slab(0, 0);
    load_slab(1, 1);

    int s_c = 0;
    int s_l = 2;
    for (int i = 0; i < nslab; i++) {
        cp_wait1();
        __syncthreads();
        if (i + 2 < nslab) load_slab(i + 2, s_l);
        else cp_commit();

        const uint32_t a_st = a_lm + (uint32_t)s_c * G_STAGE_BYTES;
        const uint32_t b_st = b_lm + (uint32_t)s_c * G_STAGE_BYTES;
#pragma unroll
        for (int ks = 0; ks < 4; ks++) {
            const uint32_t ka = a_st + ks * 32;
            uint32_t af0[4], af1[4];
            LDSM4(af0[0], af0[1], af0[2], af0[3], ka);
            LDSM4(af1[0], af1[1], af1[2], af1[3], ka + 2304);
            const uint32_t kb = b_st + ks * 32;
#pragma unroll
            for (int q = 0; q < 4; q++) {
                uint32_t b0, b1, b2, b3;
                LDSM4(b0, b1, b2, b3, kb + q * 2304);
                uint32_t bfA[2] = { b0, b2 };
                uint32_t bfB[2] = { b1, b3 };
                mma8(acc[0][2 * q],     af0, bfA);
                mma8(acc[0][2 * q + 1], af0, bfB);
                mma8(acc[1][2 * q],     af1, bfA);
                mma8(acc[1][2 * q + 1], af1, bfB);
            }
        }
        s_c++; if (s_c == 3) s_c = 0;
        s_l++; if (s_l == 3) s_l = 0;
    }

#pragma unroll
    for (int mt = 0; mt < 2; mt++) {
        int r = m0 + wm * 32 + mt * 16 + g;
#pragma unroll
        for (int nt = 0; nt < 8; nt++) {
            int c = n0 + wn * 64 + nt * 8 + tig * 2;
            float b0 = bias[c], b1 = bias[c + 1];
            float v0 = acc[mt][nt][0] + b0;
            float v1 = acc[mt][nt][1] + b1;
            float v2 = acc[mt][nt][2] + b0;
            float v3 = acc[mt][nt][3] + b1;
            if (round_out) { v0 = tf32r(v0); v1 = tf32r(v1); v2 = tf32r(v2); v3 = tf32r(v3); }
            *(float2*)(C + (size_t)r * N + c)       = make_float2(v0, v1);
            *(float2*)(C + (size_t)(r + 8) * N + c) = make_float2(v2, v3);
        }
    }
}

// ============================================================================
// Flash attention (causal): cp.async Q + double-buffered K, register-pipelined V.
// ============================================================================
#define LDQ 132
#define LDV 68
#define ATTN_SMEM_FLOATS (128 * LDQ + 2 * 64 * LDQ + 128 * LDV + 128 * LDV)
#define ATTN_SMEM_BYTES (ATTN_SMEM_FLOATS * 4)

__global__ __launch_bounds__(256) void attn_kernel(
    const float* __restrict__ qkv, float* __restrict__ out)
{
    extern __shared__ float sm[];
    float* Vst = sm + 128 * LDQ + 2 * 64 * LDQ;
    float* Ps  = Vst + 128 * LDV;

    const int tid  = threadIdx.x;
    const int lane = tid & 31;
    const int wid  = tid >> 5;
    const int g    = lane >> 2;
    const int tig  = lane & 3;
    const int rbase = wid * 16;
    const int r1 = rbase + g;
    const int r2 = r1 + 8;

    const int qt = blockIdx.x;
    const int h  = blockIdx.y;
    const int b  = blockIdx.z;
    const int q0 = qt * 128;

    const float scale = 0.08838834764831845f; // 1/sqrt(128)
    const float* Qg = qkv + (size_t)b * SEQ * QKV_N + h * D_HEAD;
    const float* Kg = Qg + D_MODEL;
    const float* Vg = Qg + 2 * D_MODEL;

    const int lmrow = lane & 15;
    const int lmc4  = (lane >> 4) * 4;
    const uint32_t sb = smem_u32(sm);
    const uint32_t q_lm  = sb + (((rbase + lmrow) * LDQ + lmc4) << 2);
    const uint32_t k_lm0 = sb + ((128 * LDQ + lmrow * LDQ + lmc4) << 2);
    const uint32_t v_lm  = sb + (((128 + 128) * LDQ + lmrow * LDV + lmc4) << 2);
    const uint32_t p_lm  = sb + (((128 + 128) * LDQ + 128 * LDV + (rbase + lmrow) * LDV + lmc4) << 2);

    const int vn  = tid & 127;
    const int vk4 = tid >> 7;

    auto load_q = [&]() {
        for (int i = tid; i < 128 * 32; i += 256) {
            int r = i >> 5;
            int c = (i & 31) * 4;
            cpasync16(sb + ((r * LDQ + c) << 2), Qg + (size_t)(q0 + r) * QKV_N + c);
        }
    };
    auto load_k = [&](int j, int buf) {
        const int kb = j * 64;
        const uint32_t kbase = sb + ((128 * LDQ + buf * 64 * LDQ) << 2);
        for (int i = tid; i < 64 * 32; i += 256) {
            int r = i >> 5;
            int c = (i & 31) * 4;
            cpasync16(kbase + ((r * LDQ + c) << 2), Kg + (size_t)(kb + r) * QKV_N + c);
        }
    };

    load_q();
    load_k(0, 0);
    cp_commit();

    float o[16][4];
#pragma unroll
    for (int nt = 0; nt < 16; nt++)
#pragma unroll
        for (int i = 0; i < 4; i++) o[nt][i] = 0.f;
    float m1 = -1e30f, m2 = -1e30f, l1 = 0.f, l2 = 0.f;

    const int njt = 2 * qt + 2;

    float4 vr[8];
#pragma unroll
    for (int t = 0; t < 8; t++) {
        int k4 = vk4 + t * 2;
        vr[t].x = Vg[(size_t)(k4 * 4 + 0) * QKV_N + vn];
        vr[t].y = Vg[(size_t)(k4 * 4 + 1) * QKV_N + vn];
        vr[t].z = Vg[(size_t)(k4 * 4 + 2) * QKV_N + vn];
        vr[t].w = Vg[(size_t)(k4 * 4 + 3) * QKV_N + vn];
    }

    for (int j = 0; j < njt; j++) {
        cp_wait0();
        __syncthreads();

#pragma unroll
        for (int t = 0; t < 8; t++)
            *(float4*)(Vst + vn * LDV + (vk4 + t * 2) * 4) = vr[t];

        if (j + 1 < njt) load_k(j + 1, (j + 1) & 1);
        cp_commit();
        __syncthreads();

        if (j + 1 < njt) {
            const float* Vt = Vg + (size_t)(j + 1) * 64 * QKV_N;
#pragma unroll
            for (int t = 0; t < 8; t++) {
                int k4 = vk4 + t * 2;
                vr[t].x = Vt[(size_t)(k4 * 4 + 0) * QKV_N + vn];
                vr[t].y = Vt[(size_t)(k4 * 4 + 1) * QKV_N + vn];
                vr[t].z = Vt[(size_t)(k4 * 4 + 2) * QKV_N + vn];
                vr[t].w = Vt[(size_t)(k4 * 4 + 3) * QKV_N + vn];
            }
        }

        const uint32_t k_lm = k_lm0 + ((j & 1) ? (uint32_t)(64 * LDQ * 4) : 0u);
        float s[8][4];
#pragma unroll
        for (int nt = 0; nt < 8; nt++)
#pragma unroll
            for (int i = 0; i < 4; i++) s[nt][i] = 0.f;

#pragma unroll
        for (int ks = 0; ks < 16; ks++) {
            uint32_t af[4];
            LDSM4(af[0], af[1], af[2], af[3], q_lm + ks * 32);
            const uint32_t kbb = k_lm + ks * 32;
#pragma unroll
            for (int q = 0; q < 4; q++) {
                uint32_t b0, b1, b2, b3;
                LDSM4(b0, b1, b2, b3, kbb + q * (16 * LDQ * 4));
                uint32_t bfA[2] = { b0, b2 };
                uint32_t bfB[2] = { b1, b3 };
                mma8(s[2 * q],     af, bfA);
                mma8(s[2 * q + 1], af, bfB);
            }
        }

#pragma unroll
        for (int nt = 0; nt < 8; nt++) {
            s[nt][0] *= scale; s[nt][1] *= scale;
            s[nt][2] *= scale; s[nt][3] *= scale;
        }

        if (j >= 2 * qt) {
            const int koff = (j - 2 * qt) << 6;
            const int lim1 = r1 - koff;
            const int lim2 = r2 - koff;
#pragma unroll
            for (int nt = 0; nt < 8; nt++) {
                int c0 = nt * 8 + tig * 2;
                if (c0     > lim1) s[nt][0] = -1e30f;
                if (c0 + 1 > lim1) s[nt][1] = -1e30f;
                if (c0     > lim2) s[nt][2] = -1e30f;
                if (c0 + 1 > lim2) s[nt][3] = -1e30f;
            }
        }

        float mx1 = -1e30f, mx2 = -1e30f;
#pragma unroll
        for (int nt = 0; nt < 8; nt++) {
            mx1 = fmaxf(mx1, fmaxf(s[nt][0], s[nt][1]));
            mx2 = fmaxf(mx2, fmaxf(s[nt][2], s[nt][3]));
        }
        mx1 = fmaxf(mx1, __shfl_xor_sync(0xffffffffu, mx1, 1));
        mx1 = fmaxf(mx1, __shfl_xor_sync(0xffffffffu, mx1, 2));
        mx2 = fmaxf(mx2, __shfl_xor_sync(0xffffffffu, mx2, 1));
        mx2 = fmaxf(mx2, __shfl_xor_sync(0xffffffffu, mx2, 2));

        const float mn1 = fmaxf(m1, mx1);
        const float mn2 = fmaxf(m2, mx2);
        const float al1 = __expf(m1 - mn1);
        const float al2 = __expf(m2 - mn2);

        float sm1 = 0.f, sm2 = 0.f;
#pragma unroll
        for (int nt = 0; nt < 8; nt++) {
            s[nt][0] = __expf(s[nt][0] - mn1);
            s[nt][1] = __expf(s[nt][1] - mn1);
            s[nt][2] = __expf(s[nt][2] - mn2);
            s[nt][3] = __expf(s[nt][3] - mn2);
            sm1 += s[nt][0] + s[nt][1];
            sm2 += s[nt][2] + s[nt][3];
        }
        sm1 += __shfl_xor_sync(0xffffffffu, sm1, 1);
        sm1 += __shfl_xor_sync(0xffffffffu, sm1, 2);
        sm2 += __shfl_xor_sync(0xffffffffu, sm2, 1);
        sm2 += __shfl_xor_sync(0xffffffffu, sm2, 2);

        l1 = al1 * l1 + sm1;
        l2 = al2 * l2 + sm2;
        m1 = mn1;
        m2 = mn2;

#pragma unroll
        for (int nt = 0; nt < 16; nt++) {
            o[nt][0] *= al1; o[nt][1] *= al1;
            o[nt][2] *= al2; o[nt][3] *= al2;
        }

#pragma unroll
        for (int nt = 0; nt < 8; nt++) {
            int c = nt * 8 + tig * 2;
            *(float2*)(Ps + r1 * LDV + c) = make_float2(tf32r(s[nt][0]), tf32r(s[nt][1]));
            *(float2*)(Ps + r2 * LDV + c) = make_float2(tf32r(s[nt][2]), tf32r(s[nt][3]));
        }
        __syncwarp();

#pragma unroll
        for (int ks = 0; ks < 8; ks++) {
            uint32_t af[4];
            LDSM4(af[0], af[1], af[2], af[3], p_lm + ks * 32);
            const uint32_t vb = v_lm + ks * 32;
#pragma unroll
            for (int q = 0; q < 8; q++) {
                uint32_t b0, b1, b2, b3;
                LDSM4(b0, b1, b2, b3, vb + q * (16 * LDV * 4));
                uint32_t bfA[2] = { b0, b2 };
                uint32_t bfB[2] = { b1, b3 };
                mma8(o[2 * q],     af, bfA);
                mma8(o[2 * q + 1], af, bfB);
            }
        }
        __syncwarp();
    }

    const float inv1 = 1.f / l1;
    const float inv2 = 1.f / l2;
    float* Og = out + ((size_t)b * SEQ + q0) * D_MODEL + h * D_HEAD;
#pragma unroll
    for (int nt = 0; nt < 16; nt++) {
        int c = nt * 8 + tig * 2;
        *(float2*)(Og + (size_t)r1 * D_MODEL + c) =
            make_float2(tf32r(o[nt][0] * inv1), tf32r(o[nt][1] * inv1));
        *(float2*)(Og + (size_t)r2 * D_MODEL + c) =
            make_float2(tf32r(o[nt][2] * inv2), tf32r(o[nt][3] * inv2));
    }
}

// ============================================================================
// Launch
// ============================================================================
extern "C" void kernel_launch(void* const* d_in, const int* in_sizes, int n_in,
                              void* d_out, int out_size) {
    const float* x    = (const float*)d_in[0];
    const float* Wqkv = (const float*)d_in[1];
    const float* bqkv = (const float*)d_in[2];
    const float* Wout = (const float*)d_in[3];
    const float* bout = (const float*)d_in[4];
    float* out = (float*)d_out;

    float *qkv_p, *att_p, *x_p, *wqkvT_p, *woutT_p;
    cudaGetSymbolAddress((void**)&qkv_p, g_qkv);
    cudaGetSymbolAddress((void**)&att_p, g_att);
    cudaGetSymbolAddress((void**)&x_p, g_x);
    cudaGetSymbolAddress((void**)&wqkvT_p, g_wqkvT);
    cudaGetSymbolAddress((void**)&woutT_p, g_woutT);

    cudaFuncSetAttribute(gemm_lm, cudaFuncAttributeMaxDynamicSharedMemorySize,
                         (int)G_SMEM_BYTES);
    cudaFuncSetAttribute(attn_kernel, cudaFuncAttributeMaxDynamicSharedMemorySize,
                         (int)ATTN_SMEM_BYTES);

    {
        int n4 = BS * D_MODEL / 4;
        round_copy4<<<(n4 + 255) / 256, 256>>>(x, x_p, n4);
        transpose_round<<<dim3(QKV_N / 32, D_MODEL / 32), dim3(32, 8)>>>(Wqkv, wqkvT_p, D_MODEL, QKV_N);
        transpose_round<<<dim3(D_MODEL / 32, D_MODEL / 32), dim3(32, 8)>>>(Wout, woutT_p, D_MODEL, D_MODEL);
    }

    gemm_lm<<<dim3(QKV_N / 128, BS / 128), 256, G_SMEM_BYTES>>>(
        x_p, wqkvT_p, bqkv, qkv_p, BS, QKV_N, D_MODEL, 1);

    attn_kernel<<<dim3(SEQ / 128, N_HEADS, BATCH), 256, ATTN_SMEM_BYTES>>>(qkv_p, att_p);

    gemm_lm<<<dim3(D_MODEL / 128, BS / 128), 256, G_SMEM_BYTES>>>(
        att_p, woutT_p, bout, out, BS, D_MODEL, D_MODEL, 0);
}